// round 13
// baseline (speedup 1.0000x reference)
#include <cuda_runtime.h>
#include <cuda_fp16.h>
#include <math.h>
#include <cstdint>

// ---------------------------------------------------------------------------
// Problem constants
// ---------------------------------------------------------------------------
#define BATCH   4
#define TSEQ    2048
#define CEMB    1024
#define NHEAD   16
#define HDIM    64
#define C3      (3*CEMB)      // 3072
#define CFF     (4*CEMB)      // 4096
#define NROWS   (BATCH*TSEQ)  // 8192
#define LN_EPS  1e-5f

// ---------------------------------------------------------------------------
// Scratch (__device__ globals; alloc-free rule)
// ---------------------------------------------------------------------------
__device__ float  g_qkv[(size_t)NROWS * C3];         // fp32 (attention input)
__device__ float  g_skq[2 * (size_t)NROWS * C3];     // QKV split-K partials
__device__ float  g_f2p[4 * (size_t)NROWS * CEMB];   // FC2 split-K partials
__device__ float  g_att[(size_t)NROWS * CEMB];
__device__ float  g_xn [(size_t)NROWS * CEMB];
__device__ __half g_xh [(size_t)NROWS * CEMB];       // x in half
__device__ __half g_xnh[(size_t)NROWS * CEMB];       // xn in half
__device__ __half g_hh [(size_t)NROWS * CFF];        // gelu(fc1) in half
__device__ __half g_wTq[(size_t)C3  * CEMB];         // [3072,1024] half K-major
__device__ __half g_wT1[(size_t)CFF * CEMB];
__device__ __half g_wT2[(size_t)CEMB * CFF];

// ---------------------------------------------------------------------------
// Helpers
// ---------------------------------------------------------------------------
__device__ __forceinline__ uint32_t smem_u32(const void* p) {
    uint32_t a;
    asm("{ .reg .u64 t; cvta.to.shared.u64 t, %1; cvt.u32.u64 %0, t; }"
        : "=r"(a) : "l"(p));
    return a;
}

#define SWZ(o) ((o) ^ (((o) >> 3) & 0x70))

__device__ __forceinline__ void ldmx4(uint32_t* r, uint32_t addr) {
    asm volatile("ldmatrix.sync.aligned.m8n8.x4.shared.b16 {%0,%1,%2,%3}, [%4];"
                 : "=r"(r[0]), "=r"(r[1]), "=r"(r[2]), "=r"(r[3]) : "r"(addr));
}

__device__ __forceinline__ void mma16816(float* d, const uint32_t* a,
                                         const uint32_t* b) {
    asm volatile(
        "mma.sync.aligned.m16n8k16.row.col.f32.f16.f16.f32 "
        "{%0,%1,%2,%3}, {%4,%5,%6,%7}, {%8,%9}, {%0,%1,%2,%3};"
        : "+f"(d[0]), "+f"(d[1]), "+f"(d[2]), "+f"(d[3])
        : "r"(a[0]), "r"(a[1]), "r"(a[2]), "r"(a[3]), "r"(b[0]), "r"(b[1]));
}

__device__ __forceinline__ void cpasync16(uint32_t s, const void* g) {
    asm volatile("cp.async.cg.shared.global [%0], [%1], 16;" :: "r"(s), "l"(g));
}
__device__ __forceinline__ void cpasync_commit() {
    asm volatile("cp.async.commit_group;" ::: "memory");
}
template<int N>
__device__ __forceinline__ void cpasync_wait() {
    asm volatile("cp.async.wait_group %0;" :: "n"(N) : "memory");
}

// ---------------------------------------------------------------------------
// GEMM: C(+z*M*N)[M,N] = A[M, kbase:kbase+kcnt] @ Bt^T + (bias) (opt GeLU).
// Emulated mma.sync core (R6/R12 champion, frozen). Split-K via blockIdx.z.
// CTA tile 128x128, BK=64 halfs, 8 warps; cp.async 3-stage; 2 CTAs/SM.
// ---------------------------------------------------------------------------
#define BK 64
#define TILE_BYTES 16384
#define STAGE_BYTES 32768
#define NSTAGE 3
#define GT_SMEM (NSTAGE * STAGE_BYTES)   // 98304

template<bool GELU, bool BIAS, typename OutT>
__global__ __launch_bounds__(256, 2)
void hgemm_kernel(const __half* __restrict__ A, const __half* __restrict__ Bt,
                  const float* __restrict__ bias, OutT* __restrict__ C,
                  int M, int N, int Kfull, int kcnt)
{
    extern __shared__ char sm[];
    const uint32_t sbase = smem_u32(sm);

    const int t    = threadIdx.x;
    const int wid  = t >> 5;
    const int lane = t & 31;
    const int wm   = wid & 1;
    const int wn   = wid >> 1;
    const int row0 = blockIdx.y * 128;
    const int col0 = blockIdx.x * 128;
    const int kbase = blockIdx.z * kcnt;
    C += (size_t)blockIdx.z * M * N;

    const int KT = kcnt / BK;

    const int srow[4] = { (t + 0)   >> 3, (t + 256) >> 3,
                          (t + 512) >> 3, (t + 768) >> 3 };
    const int sch = t & 7;
    const uint32_t sso[4] = {
        SWZ((uint32_t)(srow[0] * 128 + sch * 16)),
        SWZ((uint32_t)(srow[1] * 128 + sch * 16)),
        SWZ((uint32_t)(srow[2] * 128 + sch * 16)),
        SWZ((uint32_t)(srow[3] * 128 + sch * 16)) };

    #define ISSUE(kt, st)                                                      \
        {                                                                      \
            const int kk_ = kbase + (kt) * BK;                                 \
            const uint32_t ab = sbase + (uint32_t)(st) * STAGE_BYTES;          \
            const uint32_t bb = ab + TILE_BYTES;                               \
            _Pragma("unroll")                                                  \
            for (int it = 0; it < 4; it++) {                                   \
                cpasync16(ab + sso[it],                                        \
                    A  + (size_t)(row0 + srow[it]) * Kfull + kk_ + sch * 8);   \
                cpasync16(bb + sso[it],                                        \
                    Bt + (size_t)(col0 + srow[it]) * Kfull + kk_ + sch * 8);   \
            }                                                                  \
        }

    float d[4][4][4];
    #pragma unroll
    for (int mt = 0; mt < 4; mt++)
        #pragma unroll
        for (int nt = 0; nt < 4; nt++)
            #pragma unroll
            for (int rr = 0; rr < 4; rr++)
                d[mt][nt][rr] = 0.f;

    ISSUE(0, 0); cpasync_commit();
    ISSUE(1, 1); cpasync_commit();

    int st = 0;
    for (int kt = 0; kt < KT; kt++) {
        cpasync_wait<1>();
        __syncthreads();

        const uint32_t sa = sbase + (uint32_t)st * STAGE_BYTES;
        const uint32_t sb = sa + TILE_BYTES;

        #pragma unroll
        for (int kc = 0; kc < 4; kc++) {
            uint32_t afr[4][4];
            #pragma unroll
            for (int mt = 0; mt < 4; mt++) {
                const int arow = wm * 64 + mt * 16 + (lane & 15);
                const int ach  = kc * 2 + (lane >> 4);
                ldmx4(afr[mt], sa + SWZ((uint32_t)(arow * 128 + ach * 16)));
            }
            uint32_t bfr[2][4];
            #pragma unroll
            for (int nt2 = 0; nt2 < 2; nt2++) {
                const int brow = wn * 32 + nt2 * 16 + ((lane >> 4) << 3) + (lane & 7);
                const int bch  = kc * 2 + ((lane >> 3) & 1);
                ldmx4(bfr[nt2], sb + SWZ((uint32_t)(brow * 128 + bch * 16)));
            }
            #pragma unroll
            for (int mt = 0; mt < 4; mt++)
                #pragma unroll
                for (int nt = 0; nt < 4; nt++)
                    mma16816(d[mt][nt], afr[mt], &bfr[nt >> 1][(nt & 1) * 2]);
        }

        const int nst = (st + 2 >= NSTAGE) ? st + 2 - NSTAGE : st + 2;
        if (kt + 2 < KT) ISSUE(kt + 2, nst);
        cpasync_commit();
        st = (st + 1 == NSTAGE) ? 0 : st + 1;
    }

    const int er = lane >> 2;
    const int ec = (lane & 3) * 2;
    #pragma unroll
    for (int mt = 0; mt < 4; mt++) {
        #pragma unroll
        for (int nt = 0; nt < 4; nt++) {
            const int col = col0 + wn * 32 + nt * 8 + ec;
            const float b0 = BIAS ? bias[col]     : 0.f;
            const float b1 = BIAS ? bias[col + 1] : 0.f;
            #pragma unroll
            for (int hf = 0; hf < 2; hf++) {
                const int row = row0 + wm * 64 + mt * 16 + er + hf * 8;
                float v0 = d[mt][nt][hf * 2 + 0] + b0;
                float v1 = d[mt][nt][hf * 2 + 1] + b1;
                if (GELU) {
                    v0 = 0.5f * v0 * (1.f + erff(v0 * 0.70710678118654752f));
                    v1 = 0.5f * v1 * (1.f + erff(v1 * 0.70710678118654752f));
                }
                OutT* dst = C + (size_t)row * N + col;
                if (sizeof(OutT) == 4) {
                    *(float2*)dst = make_float2(v0, v1);
                } else {
                    *(__half2*)dst = __floats2half2_rn(v0, v1);
                }
            }
        }
    }
    #undef ISSUE
}

// ---------------------------------------------------------------------------
// qkv = p0 + p1 + bias (vectorized; bias period C3)
// ---------------------------------------------------------------------------
__global__ __launch_bounds__(256)
void reduce2_bias_kernel(const float* __restrict__ p0, const float* __restrict__ p1,
                         const float* __restrict__ bias, float* __restrict__ out)
{
    const size_t i = (size_t)blockIdx.x * 256 + threadIdx.x;   // float4 index
    const size_t n4 = (size_t)NROWS * C3 / 4;
    if (i < n4) {
        float4 a = ((const float4*)p0)[i];
        float4 b = ((const float4*)p1)[i];
        float4 bv = *(const float4*)(bias + (i * 4) % C3);
        float4 o;
        o.x = a.x + b.x + bv.x;
        o.y = a.y + b.y + bv.y;
        o.z = a.z + b.z + bv.z;
        o.w = a.w + b.w + bv.w;
        ((float4*)out)[i] = o;
    }
}

// ---------------------------------------------------------------------------
// fp32 -> fp16 convert
// ---------------------------------------------------------------------------
__global__ __launch_bounds__(256)
void f2h_kernel(const float* __restrict__ in, __half* __restrict__ out, int n4)
{
    const int i = blockIdx.x * 256 + threadIdx.x;
    if (i < n4) {
        float4 v = ((const float4*)in)[i];
        ((__half2*)out)[2*i]   = __floats2half2_rn(v.x, v.y);
        ((__half2*)out)[2*i+1] = __floats2half2_rn(v.z, v.w);
    }
}

// ---------------------------------------------------------------------------
// Weight transpose + convert: out_h[n][k] = (half) in[k][n]
// ---------------------------------------------------------------------------
__global__ __launch_bounds__(256)
void transpose_h_kernel(const float* __restrict__ in, __half* __restrict__ out,
                        int R, int Ccols)
{
    __shared__ float tile[32][33];
    const int c = blockIdx.x * 32 + threadIdx.x;
    const int r = blockIdx.y * 32 + threadIdx.y;
    #pragma unroll
    for (int i = 0; i < 32; i += 8)
        tile[threadIdx.y + i][threadIdx.x] = in[(size_t)(r + i) * Ccols + c];
    __syncthreads();
    const int oc   = blockIdx.y * 32 + threadIdx.x;
    const int orow = blockIdx.x * 32 + threadIdx.y;
    #pragma unroll
    for (int i = 0; i < 32; i += 8)
        out[(size_t)(orow + i) * R + oc] = __float2half(tile[threadIdx.x][threadIdx.y + i]);
}

// ---------------------------------------------------------------------------
// Flash attention (causal), fp32. cp.async double-buffered K/V (R12 champion).
// ---------------------------------------------------------------------------
#define ATT_P 68
#define ATT_TILE (64 * ATT_P * 4)
#define ATT_SMEM (6 * ATT_TILE)            // 104448

__global__ __launch_bounds__(256, 2)
void flash_attn_kernel(const float* __restrict__ qkv, float* __restrict__ y)
{
    extern __shared__ float smf[];
    float* Qs  = smf;
    float* Kb[2] = { smf + 64*ATT_P,  smf + 192*ATT_P };
    float* Vb[2] = { smf + 128*ATT_P, smf + 256*ATT_P };
    float* Ss  = smf + 320*ATT_P;
    const uint32_t sb = smem_u32(smf);

    const int qt = blockIdx.x;
    const int bh = blockIdx.y;
    const int b  = bh >> 4;
    const int h  = bh & 15;
    const int t  = threadIdx.x;
    const int i  = t >> 2;
    const int cg = t & 3;
    const int c0 = cg << 4;
    const int qs = qt * 64;

    const size_t base = (size_t)(b * TSEQ) * C3 + h * HDIM;

    const int sd4 = (t & 15) * 4;
    const int sr  = t >> 4;

    {
        const uint32_t kdst = sb + (uint32_t)(64*ATT_P*4);
        const uint32_t vdst = sb + (uint32_t)(128*ATT_P*4);
        #pragma unroll
        for (int rr = 0; rr < 64; rr += 16) {
            const int row = sr + rr;
            const float* kp = qkv + base + (size_t)row * C3 + CEMB + sd4;
            cpasync16(kdst + (uint32_t)((row*ATT_P + sd4)*4), kp);
            cpasync16(vdst + (uint32_t)((row*ATT_P + sd4)*4), kp + CEMB);
        }
        cpasync_commit();
        #pragma unroll
        for (int rr = 0; rr < 64; rr += 16) {
            const int row = sr + rr;
            *(float4*)&Qs[row*ATT_P + sd4] =
                *(const float4*)(qkv + base + (size_t)(qs + row) * C3 + sd4);
        }
    }

    float m = -INFINITY, l = 0.f;
    float O[16];
    #pragma unroll
    for (int j = 0; j < 16; j++) O[j] = 0.f;

    for (int kt = 0; kt <= qt; kt++) {
        cpasync_wait<0>();
        __syncthreads();

        if (kt < qt) {
            const int nb = (kt + 1) & 1;
            const int ks1 = (kt + 1) * 64;
            const uint32_t kdst = sb + (uint32_t)((64 + 128*nb)*ATT_P*4);
            const uint32_t vdst = kdst + (uint32_t)(64*ATT_P*4);
            #pragma unroll
            for (int rr = 0; rr < 64; rr += 16) {
                const int row = sr + rr;
                const float* kp = qkv + base + (size_t)(ks1 + row) * C3 + CEMB + sd4;
                cpasync16(kdst + (uint32_t)((row*ATT_P + sd4)*4), kp);
                cpasync16(vdst + (uint32_t)((row*ATT_P + sd4)*4), kp + CEMB);
            }
        }
        cpasync_commit();

        const float* Ks = Kb[kt & 1];
        const float* Vs = Vb[kt & 1];

        float acc[16];
        #pragma unroll
        for (int jj = 0; jj < 16; jj++) acc[jj] = 0.f;
        #pragma unroll 4
        for (int d4 = 0; d4 < 64; d4 += 4) {
            float4 qv = *(const float4*)&Qs[i*ATT_P + d4];
            #pragma unroll
            for (int jj = 0; jj < 16; jj++) {
                float4 kv = *(const float4*)&Ks[(c0+jj)*ATT_P + d4];
                acc[jj] += qv.x*kv.x + qv.y*kv.y + qv.z*kv.z + qv.w*kv.w;
            }
        }

        const bool diag = (kt == qt);
        float mt = -INFINITY;
        #pragma unroll
        for (int jj = 0; jj < 16; jj++) {
            float s = acc[jj] * 0.125f;
            if (diag && (c0 + jj) > i) s = -INFINITY;
            acc[jj] = s;
            mt = fmaxf(mt, s);
        }
        mt = fmaxf(mt, __shfl_xor_sync(0xffffffffu, mt, 1));
        mt = fmaxf(mt, __shfl_xor_sync(0xffffffffu, mt, 2));
        const float mnew = fmaxf(m, mt);

        float lt = 0.f;
        #pragma unroll
        for (int jj = 0; jj < 16; jj++) {
            float p = __expf(acc[jj] - mnew);
            Ss[i*ATT_P + c0 + jj] = p;
            lt += p;
        }
        lt += __shfl_xor_sync(0xffffffffu, lt, 1);
        lt += __shfl_xor_sync(0xffffffffu, lt, 2);

        const float scale = __expf(m - mnew);
        m = mnew;
        l = l * scale + lt;
        #pragma unroll
        for (int cc = 0; cc < 16; cc++) O[cc] *= scale;
        __syncwarp();

        for (int j = 0; j < 64; j++) {
            float p = Ss[i*ATT_P + j];
            const float* vrow = &Vs[j*ATT_P + c0];
            #pragma unroll
            for (int cc4 = 0; cc4 < 16; cc4 += 4) {
                float4 vv = *(const float4*)(vrow + cc4);
                O[cc4+0] = fmaf(p, vv.x, O[cc4+0]);
                O[cc4+1] = fmaf(p, vv.y, O[cc4+1]);
                O[cc4+2] = fmaf(p, vv.z, O[cc4+2]);
                O[cc4+3] = fmaf(p, vv.w, O[cc4+3]);
            }
        }
    }

    const float inv = 1.f / l;
    float* dst = y + (size_t)(b * TSEQ + qs + i) * CEMB + h * HDIM + c0;
    #pragma unroll
    for (int cc = 0; cc < 16; cc++) dst[cc] = O[cc] * inv;
}

// ---------------------------------------------------------------------------
// Fused residual-add + LayerNorm (ln1): out = LN(a + r), + half emit
// ---------------------------------------------------------------------------
__global__ __launch_bounds__(256)
void add_ln_kernel(const float* __restrict__ a, const float* __restrict__ r,
                   const float* __restrict__ gam, const float* __restrict__ bet,
                   float* __restrict__ out, __half* __restrict__ outh)
{
    const int row = blockIdx.x;
    const int t   = threadIdx.x;

    float4 va = ((const float4*)(a + (size_t)row * CEMB))[t];
    float4 vr = ((const float4*)(r + (size_t)row * CEMB))[t];
    float4 v;
    v.x = va.x + vr.x; v.y = va.y + vr.y; v.z = va.z + vr.z; v.w = va.w + vr.w;

    float s  = v.x + v.y + v.z + v.w;
    float sq = v.x*v.x + v.y*v.y + v.z*v.z + v.w*v.w;
    #pragma unroll
    for (int o = 16; o; o >>= 1) {
        s  += __shfl_xor_sync(0xffffffffu, s,  o);
        sq += __shfl_xor_sync(0xffffffffu, sq, o);
    }
    __shared__ float ps[8], pq[8];
    const int w = t >> 5, lane = t & 31;
    if (lane == 0) { ps[w] = s; pq[w] = sq; }
    __syncthreads();
    s = 0.f; sq = 0.f;
    #pragma unroll
    for (int k = 0; k < 8; k++) { s += ps[k]; sq += pq[k]; }

    const float mu   = s * (1.f / CEMB);
    const float var  = sq * (1.f / CEMB) - mu * mu;
    const float rstd = rsqrtf(var + LN_EPS);

    float4 gg = ((const float4*)gam)[t];
    float4 bb = ((const float4*)bet)[t];
    float4 o;
    o.x = (v.x - mu) * rstd * gg.x + bb.x;
    o.y = (v.y - mu) * rstd * gg.y + bb.y;
    o.z = (v.z - mu) * rstd * gg.z + bb.z;
    o.w = (v.w - mu) * rstd * gg.w + bb.w;
    ((float4*)(out + (size_t)row * CEMB))[t] = o;
    __half2* oh = (__half2*)(outh + (size_t)row * CEMB);
    oh[2*t]   = __floats2half2_rn(o.x, o.y);
    oh[2*t+1] = __floats2half2_rn(o.z, o.w);
}

// ---------------------------------------------------------------------------
// Final LN (ln2) fused with FC2 split-K reduction:
// out = LN(xn + (p0+p1+p2+p3) + bias)
// ---------------------------------------------------------------------------
__global__ __launch_bounds__(256)
void add_ln_fc2_kernel(const float* __restrict__ xn, const float* __restrict__ p,
                       const float* __restrict__ bias,
                       const float* __restrict__ gam, const float* __restrict__ bet,
                       float* __restrict__ out)
{
    const int row = blockIdx.x;
    const int t   = threadIdx.x;
    const size_t PART = (size_t)NROWS * CEMB;
    const size_t off  = (size_t)row * CEMB;

    float4 v = ((const float4*)(xn + off))[t];
    float4 bv = ((const float4*)bias)[t];
    v.x += bv.x; v.y += bv.y; v.z += bv.z; v.w += bv.w;
    #pragma unroll
    for (int z = 0; z < 4; z++) {
        float4 pv = ((const float4*)(p + z * PART + off))[t];
        v.x += pv.x; v.y += pv.y; v.z += pv.z; v.w += pv.w;
    }

    float s  = v.x + v.y + v.z + v.w;
    float sq = v.x*v.x + v.y*v.y + v.z*v.z + v.w*v.w;
    #pragma unroll
    for (int o = 16; o; o >>= 1) {
        s  += __shfl_xor_sync(0xffffffffu, s,  o);
        sq += __shfl_xor_sync(0xffffffffu, sq, o);
    }
    __shared__ float ps[8], pq[8];
    const int w = t >> 5, lane = t & 31;
    if (lane == 0) { ps[w] = s; pq[w] = sq; }
    __syncthreads();
    s = 0.f; sq = 0.f;
    #pragma unroll
    for (int k = 0; k < 8; k++) { s += ps[k]; sq += pq[k]; }

    const float mu   = s * (1.f / CEMB);
    const float var  = sq * (1.f / CEMB) - mu * mu;
    const float rstd = rsqrtf(var + LN_EPS);

    float4 gg = ((const float4*)gam)[t];
    float4 bb = ((const float4*)bet)[t];
    float4 o;
    o.x = (v.x - mu) * rstd * gg.x + bb.x;
    o.y = (v.y - mu) * rstd * gg.y + bb.y;
    o.z = (v.z - mu) * rstd * gg.z + bb.z;
    o.w = (v.w - mu) * rstd * gg.w + bb.w;
    ((float4*)(out + (size_t)row * CEMB))[t] = o;
}

// ---------------------------------------------------------------------------
// Launch
// ---------------------------------------------------------------------------
extern "C" void kernel_launch(void* const* d_in, const int* in_sizes, int n_in,
                              void* d_out, int out_size)
{
    const float* x     = (const float*)d_in[0];
    const float* w_qkv = (const float*)d_in[1];
    const float* b_qkv = (const float*)d_in[2];
    const float* ln1_g = (const float*)d_in[3];
    const float* ln1_b = (const float*)d_in[4];
    const float* w_fc1 = (const float*)d_in[5];
    const float* b_fc1 = (const float*)d_in[6];
    const float* w_fc2 = (const float*)d_in[7];
    const float* b_fc2 = (const float*)d_in[8];
    const float* ln2_g = (const float*)d_in[9];
    const float* ln2_b = (const float*)d_in[10];
    float* out = (float*)d_out;

    void *p_qkv, *p_skq, *p_f2p, *p_att, *p_xn, *p_xh, *p_xnh, *p_hh,
         *p_wq, *p_w1, *p_w2;
    cudaGetSymbolAddress(&p_qkv, g_qkv);
    cudaGetSymbolAddress(&p_skq, g_skq);
    cudaGetSymbolAddress(&p_f2p, g_f2p);
    cudaGetSymbolAddress(&p_att, g_att);
    cudaGetSymbolAddress(&p_xn,  g_xn);
    cudaGetSymbolAddress(&p_xh,  g_xh);
    cudaGetSymbolAddress(&p_xnh, g_xnh);
    cudaGetSymbolAddress(&p_hh,  g_hh);
    cudaGetSymbolAddress(&p_wq,  g_wTq);
    cudaGetSymbolAddress(&p_w1,  g_wT1);
    cudaGetSymbolAddress(&p_w2,  g_wT2);
    float*  qkv  = (float*)p_qkv;
    float*  skq  = (float*)p_skq;
    float*  f2p  = (float*)p_f2p;
    float*  att  = (float*)p_att;
    float*  xn   = (float*)p_xn;
    __half* xh   = (__half*)p_xh;
    __half* xnh  = (__half*)p_xnh;
    __half* hh   = (__half*)p_hh;
    __half* wTq  = (__half*)p_wq;
    __half* wT1  = (__half*)p_w1;
    __half* wT2  = (__half*)p_w2;

    cudaFuncSetAttribute(flash_attn_kernel,
                         cudaFuncAttributeMaxDynamicSharedMemorySize, ATT_SMEM);
    cudaFuncSetAttribute((const void*)hgemm_kernel<false, false, float>,
                         cudaFuncAttributeMaxDynamicSharedMemorySize, GT_SMEM);
    cudaFuncSetAttribute((const void*)hgemm_kernel<true, true, __half>,
                         cudaFuncAttributeMaxDynamicSharedMemorySize, GT_SMEM);

    // 0) conversions
    f2h_kernel<<<(NROWS*CEMB/4 + 255)/256, 256>>>(x, xh, NROWS*CEMB/4);
    transpose_h_kernel<<<dim3(C3/32,  CEMB/32), dim3(32,8)>>>(w_qkv, wTq, CEMB, C3);
    transpose_h_kernel<<<dim3(CFF/32, CEMB/32), dim3(32,8)>>>(w_fc1, wT1, CEMB, CFF);
    transpose_h_kernel<<<dim3(CEMB/32, CFF/32), dim3(32,8)>>>(w_fc2, wT2, CFF, CEMB);

    // 1) QKV projection, split-K=2 -> partials, then reduce+bias
    hgemm_kernel<false, false, float>
        <<<dim3(C3/128, NROWS/128, 2), 256, GT_SMEM>>>(
        xh, wTq, nullptr, skq, NROWS, C3, CEMB, CEMB/2);
    reduce2_bias_kernel<<<(int)(((size_t)NROWS*C3/4 + 255)/256), 256>>>(
        skq, skq + (size_t)NROWS*C3, b_qkv, qkv);

    // 2) causal attention (fp32, pipelined K/V)
    flash_attn_kernel<<<dim3(TSEQ/64, BATCH*NHEAD), 256, ATT_SMEM>>>(qkv, att);

    // 3) xn = LN1(x + att) (+ half copy)
    add_ln_kernel<<<NROWS, 256>>>(x, att, ln1_g, ln1_b, xn, xnh);

    // 4) h = gelu(xn @ w_fc1 + b_fc1) (half out)
    hgemm_kernel<true, true, __half>
        <<<dim3(CFF/128, NROWS/128, 1), 256, GT_SMEM>>>(
        xnh, wT1, b_fc1, hh, NROWS, CFF, CEMB, CEMB);

    // 5) mlp partials = h @ w_fc2, split-K=4
    hgemm_kernel<false, false, float>
        <<<dim3(CEMB/128, NROWS/128, 4), 256, GT_SMEM>>>(
        hh, wT2, nullptr, f2p, NROWS, CEMB, CFF, CFF/4);

    // 6) out = LN2(xn + sum(partials) + b_fc2)
    add_ln_fc2_kernel<<<NROWS, 256>>>(xn, f2p, b_fc2, ln2_g, ln2_b, out);
}

// round 14
// speedup vs baseline: 1.0155x; 1.0155x over previous
#include <cuda_runtime.h>
#include <cuda_fp16.h>
#include <math.h>
#include <cstdint>

// ---------------------------------------------------------------------------
// Problem constants
// ---------------------------------------------------------------------------
#define BATCH   4
#define TSEQ    2048
#define CEMB    1024
#define NHEAD   16
#define HDIM    64
#define C3      (3*CEMB)      // 3072
#define CFF     (4*CEMB)      // 4096
#define NROWS   (BATCH*TSEQ)  // 8192
#define LN_EPS  1e-5f

// ---------------------------------------------------------------------------
// Scratch (__device__ globals; alloc-free rule)
// ---------------------------------------------------------------------------
__device__ float  g_qkv[(size_t)NROWS * C3];         // fp32 (attention input)
__device__ float  g_f2p[4 * (size_t)NROWS * CEMB];   // FC2 split-K partials
__device__ float  g_att[(size_t)NROWS * CEMB];
__device__ float  g_xn [(size_t)NROWS * CEMB];
__device__ __half g_xh [(size_t)NROWS * CEMB];       // x in half
__device__ __half g_xnh[(size_t)NROWS * CEMB];       // xn in half
__device__ __half g_hh [(size_t)NROWS * CFF];        // gelu(fc1) in half
__device__ __half g_wTq[(size_t)C3  * CEMB];         // [3072,1024] half K-major
__device__ __half g_wT1[(size_t)CFF * CEMB];
__device__ __half g_wT2[(size_t)CEMB * CFF];

// ---------------------------------------------------------------------------
// Helpers
// ---------------------------------------------------------------------------
__device__ __forceinline__ uint32_t smem_u32(const void* p) {
    uint32_t a;
    asm("{ .reg .u64 t; cvta.to.shared.u64 t, %1; cvt.u32.u64 %0, t; }"
        : "=r"(a) : "l"(p));
    return a;
}

#define SWZ(o) ((o) ^ (((o) >> 3) & 0x70))

__device__ __forceinline__ void ldmx4(uint32_t* r, uint32_t addr) {
    asm volatile("ldmatrix.sync.aligned.m8n8.x4.shared.b16 {%0,%1,%2,%3}, [%4];"
                 : "=r"(r[0]), "=r"(r[1]), "=r"(r[2]), "=r"(r[3]) : "r"(addr));
}

__device__ __forceinline__ void mma16816(float* d, const uint32_t* a,
                                         const uint32_t* b) {
    asm volatile(
        "mma.sync.aligned.m16n8k16.row.col.f32.f16.f16.f32 "
        "{%0,%1,%2,%3}, {%4,%5,%6,%7}, {%8,%9}, {%0,%1,%2,%3};"
        : "+f"(d[0]), "+f"(d[1]), "+f"(d[2]), "+f"(d[3])
        : "r"(a[0]), "r"(a[1]), "r"(a[2]), "r"(a[3]), "r"(b[0]), "r"(b[1]));
}

__device__ __forceinline__ void cpasync16(uint32_t s, const void* g) {
    asm volatile("cp.async.cg.shared.global [%0], [%1], 16;" :: "r"(s), "l"(g));
}
__device__ __forceinline__ void cpasync_commit() {
    asm volatile("cp.async.commit_group;" ::: "memory");
}
template<int N>
__device__ __forceinline__ void cpasync_wait() {
    asm volatile("cp.async.wait_group %0;" :: "n"(N) : "memory");
}

// ---------------------------------------------------------------------------
// GEMM: C(+z*M*N)[M,N] = A[M, kbase:kbase+kcnt] @ Bt^T + (bias) (opt GeLU).
// Emulated mma.sync core (R6/R12 champion, frozen). Split-K via blockIdx.z.
// CTA tile 128x128, BK=64 halfs, 8 warps; cp.async 3-stage; 2 CTAs/SM.
// ---------------------------------------------------------------------------
#define BK 64
#define TILE_BYTES 16384
#define STAGE_BYTES 32768
#define NSTAGE 3
#define GT_SMEM (NSTAGE * STAGE_BYTES)   // 98304

template<bool GELU, bool BIAS, typename OutT>
__global__ __launch_bounds__(256, 2)
void hgemm_kernel(const __half* __restrict__ A, const __half* __restrict__ Bt,
                  const float* __restrict__ bias, OutT* __restrict__ C,
                  int M, int N, int Kfull, int kcnt)
{
    extern __shared__ char sm[];
    const uint32_t sbase = smem_u32(sm);

    const int t    = threadIdx.x;
    const int wid  = t >> 5;
    const int lane = t & 31;
    const int wm   = wid & 1;
    const int wn   = wid >> 1;
    const int row0 = blockIdx.y * 128;
    const int col0 = blockIdx.x * 128;
    const int kbase = blockIdx.z * kcnt;
    C += (size_t)blockIdx.z * M * N;

    const int KT = kcnt / BK;

    const int srow[4] = { (t + 0)   >> 3, (t + 256) >> 3,
                          (t + 512) >> 3, (t + 768) >> 3 };
    const int sch = t & 7;
    const uint32_t sso[4] = {
        SWZ((uint32_t)(srow[0] * 128 + sch * 16)),
        SWZ((uint32_t)(srow[1] * 128 + sch * 16)),
        SWZ((uint32_t)(srow[2] * 128 + sch * 16)),
        SWZ((uint32_t)(srow[3] * 128 + sch * 16)) };

    #define ISSUE(kt, st)                                                      \
        {                                                                      \
            const int kk_ = kbase + (kt) * BK;                                 \
            const uint32_t ab = sbase + (uint32_t)(st) * STAGE_BYTES;          \
            const uint32_t bb = ab + TILE_BYTES;                               \
            _Pragma("unroll")                                                  \
            for (int it = 0; it < 4; it++) {                                   \
                cpasync16(ab + sso[it],                                        \
                    A  + (size_t)(row0 + srow[it]) * Kfull + kk_ + sch * 8);   \
                cpasync16(bb + sso[it],                                        \
                    Bt + (size_t)(col0 + srow[it]) * Kfull + kk_ + sch * 8);   \
            }                                                                  \
        }

    float d[4][4][4];
    #pragma unroll
    for (int mt = 0; mt < 4; mt++)
        #pragma unroll
        for (int nt = 0; nt < 4; nt++)
            #pragma unroll
            for (int rr = 0; rr < 4; rr++)
                d[mt][nt][rr] = 0.f;

    ISSUE(0, 0); cpasync_commit();
    ISSUE(1, 1); cpasync_commit();

    int st = 0;
    for (int kt = 0; kt < KT; kt++) {
        cpasync_wait<1>();
        __syncthreads();

        const uint32_t sa = sbase + (uint32_t)st * STAGE_BYTES;
        const uint32_t sb = sa + TILE_BYTES;

        #pragma unroll
        for (int kc = 0; kc < 4; kc++) {
            uint32_t afr[4][4];
            #pragma unroll
            for (int mt = 0; mt < 4; mt++) {
                const int arow = wm * 64 + mt * 16 + (lane & 15);
                const int ach  = kc * 2 + (lane >> 4);
                ldmx4(afr[mt], sa + SWZ((uint32_t)(arow * 128 + ach * 16)));
            }
            uint32_t bfr[2][4];
            #pragma unroll
            for (int nt2 = 0; nt2 < 2; nt2++) {
                const int brow = wn * 32 + nt2 * 16 + ((lane >> 4) << 3) + (lane & 7);
                const int bch  = kc * 2 + ((lane >> 3) & 1);
                ldmx4(bfr[nt2], sb + SWZ((uint32_t)(brow * 128 + bch * 16)));
            }
            #pragma unroll
            for (int mt = 0; mt < 4; mt++)
                #pragma unroll
                for (int nt = 0; nt < 4; nt++)
                    mma16816(d[mt][nt], afr[mt], &bfr[nt >> 1][(nt & 1) * 2]);
        }

        const int nst = (st + 2 >= NSTAGE) ? st + 2 - NSTAGE : st + 2;
        if (kt + 2 < KT) ISSUE(kt + 2, nst);
        cpasync_commit();
        st = (st + 1 == NSTAGE) ? 0 : st + 1;
    }

    const int er = lane >> 2;
    const int ec = (lane & 3) * 2;
    #pragma unroll
    for (int mt = 0; mt < 4; mt++) {
        #pragma unroll
        for (int nt = 0; nt < 4; nt++) {
            const int col = col0 + wn * 32 + nt * 8 + ec;
            const float b0 = BIAS ? bias[col]     : 0.f;
            const float b1 = BIAS ? bias[col + 1] : 0.f;
            #pragma unroll
            for (int hf = 0; hf < 2; hf++) {
                const int row = row0 + wm * 64 + mt * 16 + er + hf * 8;
                float v0 = d[mt][nt][hf * 2 + 0] + b0;
                float v1 = d[mt][nt][hf * 2 + 1] + b1;
                if (GELU) {
                    v0 = 0.5f * v0 * (1.f + erff(v0 * 0.70710678118654752f));
                    v1 = 0.5f * v1 * (1.f + erff(v1 * 0.70710678118654752f));
                }
                OutT* dst = C + (size_t)row * N + col;
                if (sizeof(OutT) == 4) {
                    *(float2*)dst = make_float2(v0, v1);
                } else {
                    *(__half2*)dst = __floats2half2_rn(v0, v1);
                }
            }
        }
    }
    #undef ISSUE
}

// ---------------------------------------------------------------------------
// fp32 -> fp16 convert
// ---------------------------------------------------------------------------
__global__ __launch_bounds__(256)
void f2h_kernel(const float* __restrict__ in, __half* __restrict__ out, int n4)
{
    const int i = blockIdx.x * 256 + threadIdx.x;
    if (i < n4) {
        float4 v = ((const float4*)in)[i];
        ((__half2*)out)[2*i]   = __floats2half2_rn(v.x, v.y);
        ((__half2*)out)[2*i+1] = __floats2half2_rn(v.z, v.w);
    }
}

// ---------------------------------------------------------------------------
// Weight transpose + convert: out_h[n][k] = (half) in[k][n]
// ---------------------------------------------------------------------------
__global__ __launch_bounds__(256)
void transpose_h_kernel(const float* __restrict__ in, __half* __restrict__ out,
                        int R, int Ccols)
{
    __shared__ float tile[32][33];
    const int c = blockIdx.x * 32 + threadIdx.x;
    const int r = blockIdx.y * 32 + threadIdx.y;
    #pragma unroll
    for (int i = 0; i < 32; i += 8)
        tile[threadIdx.y + i][threadIdx.x] = in[(size_t)(r + i) * Ccols + c];
    __syncthreads();
    const int oc   = blockIdx.y * 32 + threadIdx.x;
    const int orow = blockIdx.x * 32 + threadIdx.y;
    #pragma unroll
    for (int i = 0; i < 32; i += 8)
        out[(size_t)(orow + i) * R + oc] = __float2half(tile[threadIdx.x][threadIdx.y + i]);
}

// ---------------------------------------------------------------------------
// Flash attention (causal), fp32. cp.async double-buffered K/V (R12 champion)
// + heavy-first scheduling: qt = gridDim.x-1-blockIdx.x so 32-tile CTAs
// launch first and short CTAs pack the tail wave.
// ---------------------------------------------------------------------------
#define ATT_P 68
#define ATT_TILE (64 * ATT_P * 4)
#define ATT_SMEM (6 * ATT_TILE)            // 104448

__global__ __launch_bounds__(256, 2)
void flash_attn_kernel(const float* __restrict__ qkv, float* __restrict__ y)
{
    extern __shared__ float smf[];
    float* Qs  = smf;
    float* Kb[2] = { smf + 64*ATT_P,  smf + 192*ATT_P };
    float* Vb[2] = { smf + 128*ATT_P, smf + 256*ATT_P };
    float* Ss  = smf + 320*ATT_P;
    const uint32_t sb = smem_u32(smf);

    const int qt = gridDim.x - 1 - blockIdx.x;   // heavy blocks first
    const int bh = blockIdx.y;
    const int b  = bh >> 4;
    const int h  = bh & 15;
    const int t  = threadIdx.x;
    const int i  = t >> 2;
    const int cg = t & 3;
    const int c0 = cg << 4;
    const int qs = qt * 64;

    const size_t base = (size_t)(b * TSEQ) * C3 + h * HDIM;

    const int sd4 = (t & 15) * 4;
    const int sr  = t >> 4;

    {
        const uint32_t kdst = sb + (uint32_t)(64*ATT_P*4);
        const uint32_t vdst = sb + (uint32_t)(128*ATT_P*4);
        #pragma unroll
        for (int rr = 0; rr < 64; rr += 16) {
            const int row = sr + rr;
            const float* kp = qkv + base + (size_t)row * C3 + CEMB + sd4;
            cpasync16(kdst + (uint32_t)((row*ATT_P + sd4)*4), kp);
            cpasync16(vdst + (uint32_t)((row*ATT_P + sd4)*4), kp + CEMB);
        }
        cpasync_commit();
        #pragma unroll
        for (int rr = 0; rr < 64; rr += 16) {
            const int row = sr + rr;
            *(float4*)&Qs[row*ATT_P + sd4] =
                *(const float4*)(qkv + base + (size_t)(qs + row) * C3 + sd4);
        }
    }

    float m = -INFINITY, l = 0.f;
    float O[16];
    #pragma unroll
    for (int j = 0; j < 16; j++) O[j] = 0.f;

    for (int kt = 0; kt <= qt; kt++) {
        cpasync_wait<0>();
        __syncthreads();

        if (kt < qt) {
            const int nb = (kt + 1) & 1;
            const int ks1 = (kt + 1) * 64;
            const uint32_t kdst = sb + (uint32_t)((64 + 128*nb)*ATT_P*4);
            const uint32_t vdst = kdst + (uint32_t)(64*ATT_P*4);
            #pragma unroll
            for (int rr = 0; rr < 64; rr += 16) {
                const int row = sr + rr;
                const float* kp = qkv + base + (size_t)(ks1 + row) * C3 + CEMB + sd4;
                cpasync16(kdst + (uint32_t)((row*ATT_P + sd4)*4), kp);
                cpasync16(vdst + (uint32_t)((row*ATT_P + sd4)*4), kp + CEMB);
            }
        }
        cpasync_commit();

        const float* Ks = Kb[kt & 1];
        const float* Vs = Vb[kt & 1];

        float acc[16];
        #pragma unroll
        for (int jj = 0; jj < 16; jj++) acc[jj] = 0.f;
        #pragma unroll 4
        for (int d4 = 0; d4 < 64; d4 += 4) {
            float4 qv = *(const float4*)&Qs[i*ATT_P + d4];
            #pragma unroll
            for (int jj = 0; jj < 16; jj++) {
                float4 kv = *(const float4*)&Ks[(c0+jj)*ATT_P + d4];
                acc[jj] += qv.x*kv.x + qv.y*kv.y + qv.z*kv.z + qv.w*kv.w;
            }
        }

        const bool diag = (kt == qt);
        float mt = -INFINITY;
        #pragma unroll
        for (int jj = 0; jj < 16; jj++) {
            float s = acc[jj] * 0.125f;
            if (diag && (c0 + jj) > i) s = -INFINITY;
            acc[jj] = s;
            mt = fmaxf(mt, s);
        }
        mt = fmaxf(mt, __shfl_xor_sync(0xffffffffu, mt, 1));
        mt = fmaxf(mt, __shfl_xor_sync(0xffffffffu, mt, 2));
        const float mnew = fmaxf(m, mt);

        float lt = 0.f;
        #pragma unroll
        for (int jj = 0; jj < 16; jj++) {
            float p = __expf(acc[jj] - mnew);
            Ss[i*ATT_P + c0 + jj] = p;
            lt += p;
        }
        lt += __shfl_xor_sync(0xffffffffu, lt, 1);
        lt += __shfl_xor_sync(0xffffffffu, lt, 2);

        const float scale = __expf(m - mnew);
        m = mnew;
        l = l * scale + lt;
        #pragma unroll
        for (int cc = 0; cc < 16; cc++) O[cc] *= scale;
        __syncwarp();

        for (int j = 0; j < 64; j++) {
            float p = Ss[i*ATT_P + j];
            const float* vrow = &Vs[j*ATT_P + c0];
            #pragma unroll
            for (int cc4 = 0; cc4 < 16; cc4 += 4) {
                float4 vv = *(const float4*)(vrow + cc4);
                O[cc4+0] = fmaf(p, vv.x, O[cc4+0]);
                O[cc4+1] = fmaf(p, vv.y, O[cc4+1]);
                O[cc4+2] = fmaf(p, vv.z, O[cc4+2]);
                O[cc4+3] = fmaf(p, vv.w, O[cc4+3]);
            }
        }
    }

    const float inv = 1.f / l;
    float* dst = y + (size_t)(b * TSEQ + qs + i) * CEMB + h * HDIM + c0;
    #pragma unroll
    for (int cc = 0; cc < 16; cc++) dst[cc] = O[cc] * inv;
}

// ---------------------------------------------------------------------------
// Fused residual-add + LayerNorm (ln1): out = LN(a + r), + half emit
// ---------------------------------------------------------------------------
__global__ __launch_bounds__(256)
void add_ln_kernel(const float* __restrict__ a, const float* __restrict__ r,
                   const float* __restrict__ gam, const float* __restrict__ bet,
                   float* __restrict__ out, __half* __restrict__ outh)
{
    const int row = blockIdx.x;
    const int t   = threadIdx.x;

    float4 va = ((const float4*)(a + (size_t)row * CEMB))[t];
    float4 vr = ((const float4*)(r + (size_t)row * CEMB))[t];
    float4 v;
    v.x = va.x + vr.x; v.y = va.y + vr.y; v.z = va.z + vr.z; v.w = va.w + vr.w;

    float s  = v.x + v.y + v.z + v.w;
    float sq = v.x*v.x + v.y*v.y + v.z*v.z + v.w*v.w;
    #pragma unroll
    for (int o = 16; o; o >>= 1) {
        s  += __shfl_xor_sync(0xffffffffu, s,  o);
        sq += __shfl_xor_sync(0xffffffffu, sq, o);
    }
    __shared__ float ps[8], pq[8];
    const int w = t >> 5, lane = t & 31;
    if (lane == 0) { ps[w] = s; pq[w] = sq; }
    __syncthreads();
    s = 0.f; sq = 0.f;
    #pragma unroll
    for (int k = 0; k < 8; k++) { s += ps[k]; sq += pq[k]; }

    const float mu   = s * (1.f / CEMB);
    const float var  = sq * (1.f / CEMB) - mu * mu;
    const float rstd = rsqrtf(var + LN_EPS);

    float4 gg = ((const float4*)gam)[t];
    float4 bb = ((const float4*)bet)[t];
    float4 o;
    o.x = (v.x - mu) * rstd * gg.x + bb.x;
    o.y = (v.y - mu) * rstd * gg.y + bb.y;
    o.z = (v.z - mu) * rstd * gg.z + bb.z;
    o.w = (v.w - mu) * rstd * gg.w + bb.w;
    ((float4*)(out + (size_t)row * CEMB))[t] = o;
    __half2* oh = (__half2*)(outh + (size_t)row * CEMB);
    oh[2*t]   = __floats2half2_rn(o.x, o.y);
    oh[2*t+1] = __floats2half2_rn(o.z, o.w);
}

// ---------------------------------------------------------------------------
// Final LN (ln2) fused with FC2 split-K reduction:
// out = LN(xn + (p0+p1+p2+p3) + bias)
// ---------------------------------------------------------------------------
__global__ __launch_bounds__(256)
void add_ln_fc2_kernel(const float* __restrict__ xn, const float* __restrict__ p,
                       const float* __restrict__ bias,
                       const float* __restrict__ gam, const float* __restrict__ bet,
                       float* __restrict__ out)
{
    const int row = blockIdx.x;
    const int t   = threadIdx.x;
    const size_t PART = (size_t)NROWS * CEMB;
    const size_t off  = (size_t)row * CEMB;

    float4 v = ((const float4*)(xn + off))[t];
    float4 bv = ((const float4*)bias)[t];
    v.x += bv.x; v.y += bv.y; v.z += bv.z; v.w += bv.w;
    #pragma unroll
    for (int z = 0; z < 4; z++) {
        float4 pv = ((const float4*)(p + z * PART + off))[t];
        v.x += pv.x; v.y += pv.y; v.z += pv.z; v.w += pv.w;
    }

    float s  = v.x + v.y + v.z + v.w;
    float sq = v.x*v.x + v.y*v.y + v.z*v.z + v.w*v.w;
    #pragma unroll
    for (int o = 16; o; o >>= 1) {
        s  += __shfl_xor_sync(0xffffffffu, s,  o);
        sq += __shfl_xor_sync(0xffffffffu, sq, o);
    }
    __shared__ float ps[8], pq[8];
    const int w = t >> 5, lane = t & 31;
    if (lane == 0) { ps[w] = s; pq[w] = sq; }
    __syncthreads();
    s = 0.f; sq = 0.f;
    #pragma unroll
    for (int k = 0; k < 8; k++) { s += ps[k]; sq += pq[k]; }

    const float mu   = s * (1.f / CEMB);
    const float var  = sq * (1.f / CEMB) - mu * mu;
    const float rstd = rsqrtf(var + LN_EPS);

    float4 gg = ((const float4*)gam)[t];
    float4 bb = ((const float4*)bet)[t];
    float4 o;
    o.x = (v.x - mu) * rstd * gg.x + bb.x;
    o.y = (v.y - mu) * rstd * gg.y + bb.y;
    o.z = (v.z - mu) * rstd * gg.z + bb.z;
    o.w = (v.w - mu) * rstd * gg.w + bb.w;
    ((float4*)(out + (size_t)row * CEMB))[t] = o;
}

// ---------------------------------------------------------------------------
// Launch
// ---------------------------------------------------------------------------
extern "C" void kernel_launch(void* const* d_in, const int* in_sizes, int n_in,
                              void* d_out, int out_size)
{
    const float* x     = (const float*)d_in[0];
    const float* w_qkv = (const float*)d_in[1];
    const float* b_qkv = (const float*)d_in[2];
    const float* ln1_g = (const float*)d_in[3];
    const float* ln1_b = (const float*)d_in[4];
    const float* w_fc1 = (const float*)d_in[5];
    const float* b_fc1 = (const float*)d_in[6];
    const float* w_fc2 = (const float*)d_in[7];
    const float* b_fc2 = (const float*)d_in[8];
    const float* ln2_g = (const float*)d_in[9];
    const float* ln2_b = (const float*)d_in[10];
    float* out = (float*)d_out;

    void *p_qkv, *p_f2p, *p_att, *p_xn, *p_xh, *p_xnh, *p_hh,
         *p_wq, *p_w1, *p_w2;
    cudaGetSymbolAddress(&p_qkv, g_qkv);
    cudaGetSymbolAddress(&p_f2p, g_f2p);
    cudaGetSymbolAddress(&p_att, g_att);
    cudaGetSymbolAddress(&p_xn,  g_xn);
    cudaGetSymbolAddress(&p_xh,  g_xh);
    cudaGetSymbolAddress(&p_xnh, g_xnh);
    cudaGetSymbolAddress(&p_hh,  g_hh);
    cudaGetSymbolAddress(&p_wq,  g_wTq);
    cudaGetSymbolAddress(&p_w1,  g_wT1);
    cudaGetSymbolAddress(&p_w2,  g_wT2);
    float*  qkv  = (float*)p_qkv;
    float*  f2p  = (float*)p_f2p;
    float*  att  = (float*)p_att;
    float*  xn   = (float*)p_xn;
    __half* xh   = (__half*)p_xh;
    __half* xnh  = (__half*)p_xnh;
    __half* hh   = (__half*)p_hh;
    __half* wTq  = (__half*)p_wq;
    __half* wT1  = (__half*)p_w1;
    __half* wT2  = (__half*)p_w2;

    cudaFuncSetAttribute(flash_attn_kernel,
                         cudaFuncAttributeMaxDynamicSharedMemorySize, ATT_SMEM);
    cudaFuncSetAttribute((const void*)hgemm_kernel<false, true, float>,
                         cudaFuncAttributeMaxDynamicSharedMemorySize, GT_SMEM);
    cudaFuncSetAttribute((const void*)hgemm_kernel<false, false, float>,
                         cudaFuncAttributeMaxDynamicSharedMemorySize, GT_SMEM);
    cudaFuncSetAttribute((const void*)hgemm_kernel<true, true, __half>,
                         cudaFuncAttributeMaxDynamicSharedMemorySize, GT_SMEM);

    // 0) conversions
    f2h_kernel<<<(NROWS*CEMB/4 + 255)/256, 256>>>(x, xh, NROWS*CEMB/4);
    transpose_h_kernel<<<dim3(C3/32,  CEMB/32), dim3(32,8)>>>(w_qkv, wTq, CEMB, C3);
    transpose_h_kernel<<<dim3(CFF/32, CEMB/32), dim3(32,8)>>>(w_fc1, wT1, CEMB, CFF);
    transpose_h_kernel<<<dim3(CEMB/32, CFF/32), dim3(32,8)>>>(w_fc2, wT2, CFF, CEMB);

    // 1) QKV projection (direct, bias in epilogue)
    hgemm_kernel<false, true, float>
        <<<dim3(C3/128, NROWS/128, 1), 256, GT_SMEM>>>(
        xh, wTq, b_qkv, qkv, NROWS, C3, CEMB, CEMB);

    // 2) causal attention (fp32, pipelined K/V, heavy-first)
    flash_attn_kernel<<<dim3(TSEQ/64, BATCH*NHEAD), 256, ATT_SMEM>>>(qkv, att);

    // 3) xn = LN1(x + att) (+ half copy)
    add_ln_kernel<<<NROWS, 256>>>(x, att, ln1_g, ln1_b, xn, xnh);

    // 4) h = gelu(xn @ w_fc1 + b_fc1) (half out)
    hgemm_kernel<true, true, __half>
        <<<dim3(CFF/128, NROWS/128, 1), 256, GT_SMEM>>>(
        xnh, wT1, b_fc1, hh, NROWS, CFF, CEMB, CEMB);

    // 5) mlp partials = h @ w_fc2, split-K=4 (clean 6.92 waves vs 1.73)
    hgemm_kernel<false, false, float>
        <<<dim3(CEMB/128, NROWS/128, 4), 256, GT_SMEM>>>(
        hh, wT2, nullptr, f2p, NROWS, CEMB, CFF, CFF/4);

    // 6) out = LN2(xn + sum(partials) + b_fc2)
    add_ln_fc2_kernel<<<NROWS, 256>>>(xn, f2p, b_fc2, ln2_g, ln2_b, out);
}